// round 9
// baseline (speedup 1.0000x reference)
#include <cuda_runtime.h>
#include <math.h>
#include <stdint.h>

// Problem constants
#define Tt   512
#define Bb   64
#define Dd   256
#define Uu   512
#define Mm   64
#define NZt  2112   // 4*U + M

#define NUBLK 128   // u-blocks: 4 u-cols each (16 z-cols)
#define NEBLK 8     // e-blocks: 8 e-cols each
#define NBLK  136
#define NTHR  544   // 512 GEMM threads + 1 gate warp

// ---------------- device scratch ----------------
__device__ float g_Z[(size_t)Tt * NZt * Bb];   // Z[t][n][b]
__device__ float g_hT[2][Bb][Uu];              // hidden state [b][u], double buffered
__device__ float g_ze[Bb][Mm];                 // pre-softmax e logits

struct __align__(128) Cnt { unsigned int v; unsigned int pad[31]; };
__device__ Cnt g_harr[8];                      // per-chunk h arrival counters (16 producers each)
__device__ Cnt g_earr;                         // e arrival counter (8 producers)
__device__ Cnt g_eepoch;                       // e epoch word (1 producer)

// SMEM float offsets
#define OFF_US   0              // u: [512k][16c]=8192 ; e: [512k][8c]=4096
#define OFF_CR   8192           // cring [64 slot][4 u][64 b] = 16384
#define OFF_H    24576          // 4 h buffers x [64 b][68] = 17408
#define OFF_ZT   41984          // zt [16 c][65] = 1040
#define OFF_PS   43024          // partial-sum buffer = 1040
#define OFF_ZES  44064          // softmax probs [64 b][65] = 4160
#define OFF_HST  48224          // h staging [4 uul][64 b] = 256
#define OFF_GF   48480          // 16 flag words (0-7: h chunks, 8: e epoch)
#define SMEM_F   48496          // 193984 bytes

// ---------------- PTX helpers ----------------
__device__ __forceinline__ void cp16(uint32_t dst, const float* src) {
    asm volatile("cp.async.cg.shared.global [%0], [%1], 16;" :: "r"(dst), "l"(src));
}
__device__ __forceinline__ void cp_commit() { asm volatile("cp.async.commit_group;"); }
__device__ __forceinline__ void cp_wait0()  { asm volatile("cp.async.wait_group 0;"); }
__device__ __forceinline__ unsigned ld_acq(const unsigned int* p) {
    unsigned v;
    asm volatile("ld.acquire.gpu.global.u32 %0, [%1];" : "=r"(v) : "l"(p));
    return v;
}
__device__ __forceinline__ void red_rel(unsigned int* p) {
    asm volatile("red.release.gpu.global.add.u32 [%0], 1;" :: "l"(p));
}
__device__ __forceinline__ void st_rel_g(unsigned int* p, unsigned v) {
    asm volatile("st.release.gpu.global.u32 [%0], %1;" :: "l"(p), "r"(v));
}
__device__ __forceinline__ unsigned ld_acq_sh(const unsigned int* p) {
    unsigned v, a = (unsigned)__cvta_generic_to_shared(p);
    asm volatile("ld.acquire.cta.shared.u32 %0, [%1];" : "=r"(v) : "r"(a));
    return v;
}
__device__ __forceinline__ void st_rel_sh(unsigned int* p, unsigned v) {
    unsigned a = (unsigned)__cvta_generic_to_shared(p);
    asm volatile("st.release.cta.shared.u32 [%0], %1;" :: "r"(a), "r"(v));
}
#define NBAR() asm volatile("bar.sync 1, 512;" ::: "memory")

// packed fp32x2 FMA (FFMA2)
__device__ __forceinline__ unsigned long long pack2(float a, float b) {
    unsigned long long r;
    asm("mov.b64 %0, {%1, %2};" : "=l"(r) : "f"(a), "f"(b));
    return r;
}
__device__ __forceinline__ void fma2(unsigned long long& d,
                                     unsigned long long a, unsigned long long b) {
    asm("fma.rn.f32x2 %0, %1, %2, %0;" : "+l"(d) : "l"(a), "l"(b));
}
__device__ __forceinline__ void unpack2(unsigned long long v, float& a, float& b) {
    asm("mov.b64 {%0, %1}, %2;" : "=f"(a), "=f"(b) : "l"(v));
}

// ---------------- init ----------------
__global__ void init_kernel() {
    int tid = blockIdx.x * blockDim.x + threadIdx.x;
    float* h0 = &g_hT[0][0][0];
    for (int i = tid; i < 2 * Bb * Uu; i += gridDim.x * blockDim.x) h0[i] = 0.0f;
    if (tid < 8) g_harr[tid].v = 0u;
    if (tid == 8) g_earr.v = 0u;
    if (tid == 9) g_eepoch.v = 0u;
}

// ---------------- precompute (unchanged from R7) ----------------
__global__ __launch_bounds__(256) void precompute_kernel(
    const float* __restrict__ x,
    const float* __restrict__ Wi, const float* __restrict__ Wf,
    const float* __restrict__ Wo, const float* __restrict__ Wc,
    const float* __restrict__ We,
    const float* __restrict__ bi, const float* __restrict__ bf,
    const float* __restrict__ bo, const float* __restrict__ bc,
    const float* __restrict__ be)
{
    __shared__ float xs[64 * 65];
    __shared__ float Ws[64 * 64];

    const int nt  = blockIdx.x;
    const int t   = blockIdx.y;
    const int tid = threadIdx.x;

    const float* W; const float* bv;
    switch (nt >> 3) {
        case 0:  W = Wi; bv = bi; break;
        case 1:  W = Wf; bv = bf; break;
        case 2:  W = Wo; bv = bo; break;
        case 3:  W = Wc; bv = bc; break;
        default: W = We; bv = be; break;
    }
    const int stride = (nt < 32) ? Uu : Mm;
    const int col0   = (nt & 7) * 64;

    const int tx = tid & 15, ty = tid >> 4;

    unsigned long long acc01[4], acc23[4];
    {
        unsigned long long p01 = pack2(bv[col0 + tx * 4 + 0], bv[col0 + tx * 4 + 1]);
        unsigned long long p23 = pack2(bv[col0 + tx * 4 + 2], bv[col0 + tx * 4 + 3]);
        #pragma unroll
        for (int i = 0; i < 4; i++) { acc01[i] = p01; acc23[i] = p23; }
    }

    for (int kb = 0; kb < 4; kb++) {
        __syncthreads();
        #pragma unroll
        for (int l = 0; l < 16; l++) {
            int idx = l * 256 + tid;
            int b = idx >> 6, kk = idx & 63;
            xs[b * 65 + kk] = x[(size_t)b * Tt * Dd + (size_t)t * Dd + kb * 64 + kk];
        }
        #pragma unroll
        for (int l = 0; l < 16; l++) {
            int idx = l * 256 + tid;
            int kk = idx >> 6, nn = idx & 63;
            Ws[kk * 64 + nn] = W[(size_t)(kb * 64 + kk) * stride + col0 + nn];
        }
        __syncthreads();
        #pragma unroll 16
        for (int kk = 0; kk < 64; kk++) {
            ulonglong2 wv = *reinterpret_cast<const ulonglong2*>(&Ws[kk * 64 + tx * 4]);
            #pragma unroll
            for (int i = 0; i < 4; i++) {
                float xv = xs[(ty * 4 + i) * 65 + kk];
                unsigned long long xx = pack2(xv, xv);
                fma2(acc01[i], xx, wv.x);
                fma2(acc23[i], xx, wv.y);
            }
        }
    }

    float a[4][4];
    #pragma unroll
    for (int i = 0; i < 4; i++) {
        unpack2(acc01[i], a[i][0], a[i][1]);
        unpack2(acc23[i], a[i][2], a[i][3]);
    }
    #pragma unroll
    for (int j = 0; j < 4; j++) {
        int n = nt * 64 + tx * 4 + j;
        float4 v = make_float4(a[0][j], a[1][j], a[2][j], a[3][j]);
        *reinterpret_cast<float4*>(&g_Z[((size_t)t * NZt + n) * Bb + ty * 4]) = v;
    }
}

// ---------------- persistent recurrent kernel ----------------
__global__ __launch_bounds__(NTHR, 1) void recur_kernel(
    float* __restrict__ out,
    const float* __restrict__ Ui, const float* __restrict__ Uf,
    const float* __restrict__ Uo, const float* __restrict__ Uc,
    const float* __restrict__ Ue)
{
    extern __shared__ float sm[];
    float* Us  = sm + OFF_US;
    float* cr  = sm + OFF_CR;
    float* zt  = sm + OFF_ZT;
    float* ps  = sm + OFF_PS;
    float* zes = sm + OFF_ZES;
    float* hst = sm + OFF_HST;
    unsigned int* gf = (unsigned int*)(sm + OFF_GF);

    const uint32_t smem_u = (uint32_t)__cvta_generic_to_shared(sm);

    const int bid = blockIdx.x;
    const int tid = threadIdx.x;
    const bool isE = (bid >= NUBLK);

    // ======== gate warp (tids 512..543): never touches named barrier 1 ========
    if (tid >= 512) {
        const int lane = tid - 512;
        if (lane < 8) {
            // chunk gate: publish "h(t) chunk[lane] ready"
            for (int t = 1; t < Tt; t++) {
                while (ld_acq(&g_harr[lane].v) < 16u * (unsigned)t) { }
                st_rel_sh(&gf[lane], (unsigned)t);
            }
        } else if (lane == 8 && !isE) {
            // e-epoch gate: publish "ze(t) ready"
            for (int t = 0; t < Tt; t++) {
                while (ld_acq(&g_eepoch.v) < (unsigned)(t + 1)) { }
                st_rel_sh(&gf[8], (unsigned)(t + 1));
            }
        }
        return;
    }

    // zero smem flags (gate warp's first write is ≥1 full step away)
    if (tid < 16) gf[tid] = 0u;

    // --- load persistent U slice (once) ---
    if (!isE) {
        const int u0 = bid * 4;
        const int tc = tid & 15;                 // column c = gate*4 + uul
        const float* Ug;
        switch (tc >> 2) {
            case 0:  Ug = Ui; break;
            case 1:  Ug = Uf; break;
            case 2:  Ug = Uo; break;
            default: Ug = Uc; break;
        }
        const int lc = u0 + (tc & 3);
        for (int k = tid >> 4; k < Uu; k += 32)
            Us[k * 16 + tc] = Ug[(size_t)k * Uu + lc];
    } else {
        const int m0 = (bid - NUBLK) * 8;
        const int tc = tid & 7;
        for (int k = tid >> 3; k < Uu; k += 64)
            Us[k * 8 + tc] = Ue[(size_t)k * Mm + m0 + tc];
    }
    NBAR();

    // thread maps (512 GEMM threads)
    const int half = tid >> 8;                    // K half
    const int tx   = tid & 3;
    const int ty   = (tid >> 2) & 63;
    const int b3   = bid & 3;                     // chunk rotation start
    // fill map: row ty, 16-float segment tx
    float* const hbufs = sm + OFF_H + half * 2 * 4352;
    const uint32_t hdst0 = smem_u + (uint32_t)(OFF_H + (half * 2 + 0) * 4352 + ty * 68 + tx * 16) * 4;
    const uint32_t hdst1 = smem_u + (uint32_t)(OFF_H + (half * 2 + 1) * 4352 + ty * 68 + tx * 16) * 4;

    for (int t = 0; t < Tt; t++) {
        const float* hsrc = &g_hT[t & 1][0][0];   // [64 b][512 u]

        if (!isE) {
            const int u0 = bid * 4;

            // Z loads (independent of h)
            float zl0 = 0.f, zl1 = 0.f, zl2 = 0.f, zl3 = 0.f;
            if (half == 0) {
                const float* zp = &g_Z[((size_t)t * NZt + tx * Uu + u0) * Bb + ty];
                zl0 = __ldcs(zp);
                zl1 = __ldcs(zp + 64);
                zl2 = __ldcs(zp + 128);
                zl3 = __ldcs(zp + 192);
            }

            // prologue: gate chunk lrr(0), prefetch it
            {
                int lrr = b3;
                while (ld_acq_sh(&gf[half * 4 + lrr]) < (unsigned)t) { }
                const float* s = hsrc + (size_t)ty * Uu + half * 256 + lrr * 64 + tx * 16;
                #pragma unroll
                for (int j = 0; j < 4; j++) cp16(hdst0 + j * 16, s + j * 4);
                cp_commit();
            }

            unsigned long long acc01 = 0ull, acc23 = 0ull;

            // ---- GEMM: 4 rounds, rotated chunks, one bar per round ----
            for (int r = 0; r < 4; r++) {
                cp_wait0();
                NBAR();                          // chunk r data visible; prev buffer free
                if (r < 3) {
                    int lrr = (b3 + r + 1) & 3;
                    while (ld_acq_sh(&gf[half * 4 + lrr]) < (unsigned)t) { }
                    const float* s = hsrc + (size_t)ty * Uu + half * 256 + lrr * 64 + tx * 16;
                    uint32_t d = ((r & 1) == 0) ? hdst1 : hdst0;
                    #pragma unroll
                    for (int j = 0; j < 4; j++) cp16(d + j * 16, s + j * 4);
                    cp_commit();
                }
                const int lrr = (b3 + r) & 3;
                const float* hp = hbufs + (r & 1) * 4352 + ty * 68;
                const float* Ub = &Us[(half * 256 + lrr * 64) * 16 + tx * 4];
                #pragma unroll
                for (int kk = 0; kk < 64; kk += 2) {
                    float2 hv = *reinterpret_cast<const float2*>(&hp[kk]);
                    ulonglong2 ua = *reinterpret_cast<const ulonglong2*>(&Ub[kk * 16]);
                    ulonglong2 ub = *reinterpret_cast<const ulonglong2*>(&Ub[kk * 16 + 16]);
                    unsigned long long h0 = pack2(hv.x, hv.x);
                    unsigned long long h1 = pack2(hv.y, hv.y);
                    fma2(acc01, h0, ua.x);
                    fma2(acc23, h0, ua.y);
                    fma2(acc01, h1, ub.x);
                    fma2(acc23, h1, ub.y);
                }
            }

            // epilogue: half1 stashes partials; everyone waits e-flag (smem)
            {
                float a0, a1, a2, a3;
                unpack2(acc01, a0, a1);
                unpack2(acc23, a2, a3);
                if (half == 1) {
                    ps[(tx * 4 + 0) * 65 + ty] = a0;
                    ps[(tx * 4 + 1) * 65 + ty] = a1;
                    ps[(tx * 4 + 2) * 65 + ty] = a2;
                    ps[(tx * 4 + 3) * 65 + ty] = a3;
                }
                while (ld_acq_sh(&gf[8]) < (unsigned)(t + 1)) { }
                NBAR();
                if (half == 0) {
                    zt[(tx * 4 + 0) * 65 + ty] = a0 + ps[(tx * 4 + 0) * 65 + ty] + zl0;
                    zt[(tx * 4 + 1) * 65 + ty] = a1 + ps[(tx * 4 + 1) * 65 + ty] + zl1;
                    zt[(tx * 4 + 2) * 65 + ty] = a2 + ps[(tx * 4 + 2) * 65 + ty] + zl2;
                    zt[(tx * 4 + 3) * 65 + ty] = a3 + ps[(tx * 4 + 3) * 65 + ty] + zl3;
                }
            }

            // ---- softmax: 8 lanes per batch row, direct from L2 ----
            {
                const int sb = tid >> 3, sq = tid & 7;
                const float4* zrow = reinterpret_cast<const float4*>(&g_ze[sb][sq * 8]);
                float4 v0 = __ldcg(zrow);
                float4 v1 = __ldcg(zrow + 1);
                float v[8] = {v0.x, v0.y, v0.z, v0.w, v1.x, v1.y, v1.z, v1.w};
                float mx = -1e30f;
                #pragma unroll
                for (int i = 0; i < 8; i++) mx = fmaxf(mx, v[i]);
                mx = fmaxf(mx, __shfl_xor_sync(0xffffffffu, mx, 1));
                mx = fmaxf(mx, __shfl_xor_sync(0xffffffffu, mx, 2));
                mx = fmaxf(mx, __shfl_xor_sync(0xffffffffu, mx, 4));
                float s = 0.f;
                #pragma unroll
                for (int i = 0; i < 8; i++) { v[i] = __expf(v[i] - mx); s += v[i]; }
                s += __shfl_xor_sync(0xffffffffu, s, 1);
                s += __shfl_xor_sync(0xffffffffu, s, 2);
                s += __shfl_xor_sync(0xffffffffu, s, 4);
                float inv = 1.0f / s;
                #pragma unroll
                for (int i = 0; i < 8; i++) zes[sb * 65 + sq * 8 + i] = v[i] * inv;
            }
            NBAR();                              // zt + zes ready

            // ---- phase 2: memory read, m-loop split across halves ----
            const int item = tid & 255;
            {
                const int uul = item >> 6, b = item & 63;
                const int mlim = (t < 64) ? t : 64;
                const int lo = half * 32;
                const int hi = (mlim < lo + 32) ? mlim : lo + 32;
                float p = 0.f;
                const float* zr = &zes[b * 65];
                #pragma unroll 4
                for (int m = lo; m < hi; m++)
                    p += zr[m] * cr[(((t - 1 - m) & 63) * 4 + uul) * 64 + b];
                if (half == 1) ps[item] = p;
                NBAR();
                if (half == 0) {
                    float mc = p + ps[item];
                    float iv = zt[(uul)      * 65 + b];
                    float fv = zt[(4 + uul)  * 65 + b];
                    float ov = zt[(8 + uul)  * 65 + b];
                    float cv = zt[(12 + uul) * 65 + b];
                    iv = 1.0f / (1.0f + __expf(-iv));
                    fv = 1.0f / (1.0f + __expf(-fv));
                    ov = 1.0f / (1.0f + __expf(-ov));
                    cv = tanhf(cv);
                    float c = fv * mc + iv * cv;
                    float h = ov * tanhf(c);
                    cr[((t & 63) * 4 + uul) * 64 + b] = c;
                    hst[uul * 64 + b] = h;
                }
            }
            NBAR();
            // vectorized h + out stores (STG.128)
            if (tid < 64) {
                const int b = tid;
                float4 hv = make_float4(hst[b], hst[64 + b], hst[128 + b], hst[192 + b]);
                *reinterpret_cast<float4*>(&g_hT[(t + 1) & 1][b][u0]) = hv;
                *reinterpret_cast<float4*>(&out[((size_t)b * Tt + t) * Uu + u0]) = hv;
            }
            NBAR();
            if (tid == 0) red_rel(&g_harr[bid >> 4].v);   // chunk arrival
        } else {
            // ---- e-block: ze GEMM (8 cols, split-K, rotated chunks) ----
            const int m0 = (bid - NUBLK) * 8;
            const int c0 = tx * 2;
            float zl0 = 0.f, zl1 = 0.f;
            if (half == 0) {
                zl0 = __ldcs(&g_Z[((size_t)t * NZt + 4 * Uu + m0 + c0) * Bb + ty]);
                zl1 = __ldcs(&g_Z[((size_t)t * NZt + 4 * Uu + m0 + c0 + 1) * Bb + ty]);
            }

            // prologue
            {
                int lrr = b3;
                while (ld_acq_sh(&gf[half * 4 + lrr]) < (unsigned)t) { }
                const float* s = hsrc + (size_t)ty * Uu + half * 256 + lrr * 64 + tx * 16;
                #pragma unroll
                for (int j = 0; j < 4; j++) cp16(hdst0 + j * 16, s + j * 4);
                cp_commit();
            }
            unsigned long long accE = 0ull;
            for (int r = 0; r < 4; r++) {
                cp_wait0();
                NBAR();
                if (r < 3) {
                    int lrr = (b3 + r + 1) & 3;
                    while (ld_acq_sh(&gf[half * 4 + lrr]) < (unsigned)t) { }
                    const float* s = hsrc + (size_t)ty * Uu + half * 256 + lrr * 64 + tx * 16;
                    uint32_t d = ((r & 1) == 0) ? hdst1 : hdst0;
                    #pragma unroll
                    for (int j = 0; j < 4; j++) cp16(d + j * 16, s + j * 4);
                    cp_commit();
                }
                const int lrr = (b3 + r) & 3;
                const float* hp = hbufs + (r & 1) * 4352 + ty * 68;
                const float* Up = &Us[(half * 256 + lrr * 64) * 8 + c0];
                #pragma unroll
                for (int kk = 0; kk < 64; kk += 2) {
                    float2 hv = *reinterpret_cast<const float2*>(&hp[kk]);
                    unsigned long long u0v = *reinterpret_cast<const unsigned long long*>(&Up[kk * 8]);
                    unsigned long long u1v = *reinterpret_cast<const unsigned long long*>(&Up[(kk + 1) * 8]);
                    fma2(accE, pack2(hv.x, hv.x), u0v);
                    fma2(accE, pack2(hv.y, hv.y), u1v);
                }
            }
            float a0, a1;
            unpack2(accE, a0, a1);
            const int item = tid & 255;
            if (half == 1) { ps[item * 2] = a0; ps[item * 2 + 1] = a1; }
            NBAR();
            if (half == 0) {
                g_ze[ty][m0 + c0]     = a0 + ps[item * 2]     + zl0;
                g_ze[ty][m0 + c0 + 1] = a1 + ps[item * 2 + 1] + zl1;
            }
            NBAR();
            if (tid == 0) {
                red_rel(&g_earr.v);
                if (bid == NUBLK) {              // e-aggregator: publish epoch
                    while (ld_acq(&g_earr.v) < 8u * (unsigned)(t + 1)) { }
                    st_rel_g(&g_eepoch.v, (unsigned)(t + 1));
                }
            }
        }
    }
}

// ---------------- launch ----------------
extern "C" void kernel_launch(void* const* d_in, const int* in_sizes, int n_in,
                              void* d_out, int out_size) {
    (void)in_sizes; (void)n_in; (void)out_size;
    const float* x  = (const float*)d_in[0];
    const float* Wi = (const float*)d_in[1];
    const float* Ui = (const float*)d_in[2];
    const float* bi = (const float*)d_in[3];
    const float* Wf = (const float*)d_in[4];
    const float* Uf = (const float*)d_in[5];
    const float* bf = (const float*)d_in[6];
    const float* Wo = (const float*)d_in[7];
    const float* Uo = (const float*)d_in[8];
    const float* bo = (const float*)d_in[9];
    const float* Wc = (const float*)d_in[10];
    const float* Uc = (const float*)d_in[11];
    const float* bc = (const float*)d_in[12];
    const float* We = (const float*)d_in[13];
    const float* Ue = (const float*)d_in[14];
    const float* be = (const float*)d_in[15];
    float* out = (float*)d_out;

    const size_t SMEM = (size_t)SMEM_F * sizeof(float);   // 193984 B
    cudaFuncSetAttribute(recur_kernel, cudaFuncAttributeMaxDynamicSharedMemorySize, (int)SMEM);

    init_kernel<<<32, 256>>>();
    dim3 pg(33, Tt);
    precompute_kernel<<<pg, 256>>>(x, Wi, Wf, Wo, Wc, We, bi, bf, bo, bc, be);
    recur_kernel<<<NBLK, NTHR, SMEM>>>(out, Ui, Uf, Uo, Uc, Ue);
}